// round 3
// baseline (speedup 1.0000x reference)
#include <cuda_runtime.h>
#include <math.h>

#define BB 32
#define SS 512
#define HH 768
#define MC 128
#define EPSF 1e-8f
#define TK 16

typedef unsigned long long u64;

// ---------------- f32x2 packed-math helpers ----------------
__device__ __forceinline__ u64 pk2(float x, float y) {
    u64 r;
    asm("mov.b64 %0, {%1, %2};" : "=l"(r)
        : "r"(__float_as_uint(x)), "r"(__float_as_uint(y)));
    return r;
}
__device__ __forceinline__ void upk2(u64 v, float& x, float& y) {
    unsigned int a, b;
    asm("mov.b64 {%0, %1}, %2;" : "=r"(a), "=r"(b) : "l"(v));
    x = __uint_as_float(a); y = __uint_as_float(b);
}
__device__ __forceinline__ u64 fma2(u64 a, u64 b, u64 c) {
    u64 d;
    asm("fma.rn.f32x2 %0, %1, %2, %3;" : "=l"(d) : "l"(a), "l"(b), "l"(c));
    return d;
}
__device__ __forceinline__ u64 add2(u64 a, u64 b) {
    u64 d;
    asm("add.rn.f32x2 %0, %1, %2;" : "=l"(d) : "l"(a), "l"(b));
    return d;
}
__device__ __forceinline__ u64 relu2(u64 v) {
    float x, y; upk2(v, x, y);
    return pk2(fmaxf(x, 0.0f), fmaxf(y, 0.0f));
}

// ---------------- scratch (static device memory; no allocs) ----------------
__device__ float g_keyconf[BB*SS];
__device__ float g_valconf[BB*SS];
__device__ int   g_kidx[BB*MC];
__device__ int   g_vidx[BB*MC];
__device__ float g_kbox[BB*MC*4];
__device__ float g_vbox[BB*MC*4];
__device__ float g_valreps[BB*MC*HH];
__device__ float g_tmp[BB*MC*HH];
__device__ float g_biaf[BB*MC*MC];
__device__ float g_Wc[HH*HH];
__device__ float g_bc[HH];

// ---------------- 1) softmax + argmax + mask ----------------
__global__ void conf_kernel(const float* __restrict__ logits,
                            const int* __restrict__ mask) {
    int t = blockIdx.x * blockDim.x + threadIdx.x;
    if (t >= BB * SS) return;
    float l0 = logits[3*t+0], l1 = logits[3*t+1], l2 = logits[3*t+2];
    int pred = 0; float best = l0;
    if (l1 > best) { pred = 1; best = l1; }
    if (l2 > best) { pred = 2; best = l2; }
    float e0 = expf(l0 - best), e1 = expf(l1 - best), e2 = expf(l2 - best);
    float inv = 1.0f / (e0 + e1 + e2);
    bool valid = (mask[t] == 1);
    float ninf = -INFINITY;
    g_keyconf[t] = (pred == 1 && valid) ? e1 * inv : ninf;
    g_valconf[t] = (pred == 2 && valid) ? e2 * inv : ninf;
}

// ---------------- 2) exact top-128 of 512 via bitonic sort ----------------
__global__ void topk_kernel(const float* __restrict__ bboxes,
                            float* __restrict__ out) {
    int b = blockIdx.x;
    int which = blockIdx.y;   // 0 = key, 1 = val
    const float* conf = (which == 0) ? g_keyconf : g_valconf;
    __shared__ float sc[512];
    __shared__ int   si[512];
    int tid = threadIdx.x;
    sc[tid] = conf[b * SS + tid];
    si[tid] = tid;

    for (int k = 2; k <= 512; k <<= 1) {
        for (int j = k >> 1; j > 0; j >>= 1) {
            __syncthreads();
            int ixj = tid ^ j;
            if (ixj > tid) {
                float c1 = sc[tid], c2 = sc[ixj];
                int   i1 = si[tid], i2 = si[ixj];
                bool b2 = (c2 > c1) || (c2 == c1 && i2 < i1);
                bool doswap = ((tid & k) == 0) ? b2 : !b2;
                if (doswap) {
                    sc[tid] = c2; si[tid] = i2;
                    sc[ixj] = c1; si[ixj] = i1;
                }
            }
        }
    }
    __syncthreads();

    if (tid < MC) {
        int   idx = si[tid];
        float cf  = sc[tid];
        int*   gi = (which == 0) ? g_kidx : g_vidx;
        float* gb = (which == 0) ? g_kbox : g_vbox;
        gi[b * MC + tid] = idx;
        const float* src = bboxes + ((long long)b * SS + idx) * 4;
        float* dst = gb + (b * MC + tid) * 4;
        dst[0] = src[0]; dst[1] = src[1]; dst[2] = src[2]; dst[3] = src[3];
        long long base = (long long)BB * MC * MC;            // 524288
        float vf = (cf != -INFINITY) ? 1.0f : 0.0f;
        out[base + (long long)which * (BB * MC) + b * MC + tid] = vf;
        out[base + 2LL * (BB * MC) + (long long)which * (BB * MC) + b * MC + tid] = (float)idx;
    }
}

// ---------------- bc[j] = sum_h bk[h] * Wbil[h,j] ----------------
__global__ void bc_kernel(const float* __restrict__ bk,
                          const float* __restrict__ Wbil) {
    int j = blockIdx.x * 128 + threadIdx.x;
    float s = 0.0f;
    for (int h = 0; h < HH; h++) s = fmaf(bk[h], Wbil[h * HH + j], s);
    g_bc[j] = s;
}

// ======= shared inner-product macro pieces (packed FFMA2 microkernel) =======
// acc2[i2][j]: lo lane = row ty*8+2*i2, hi lane = row ty*8+2*i2+1; col tx*8+j

// ---------------- 3a) Wc = Wk @ Wbil, split-K, atomic accumulate ----------
__global__ __launch_bounds__(256)
void wc_splitk(const float* __restrict__ A, const float* __restrict__ Bm) {
    __shared__ __align__(16) float As[2][TK][132];
    __shared__ __align__(16) float Bs[2][TK][128];
    int tid = threadIdx.x;
    int tx = tid & 15, ty = tid >> 4;
    int m0 = blockIdx.y * 128, c0 = blockIdx.x * 128;
    int kbase = blockIdx.z * (HH / 4);       // 192 per split
    int ar0 = tid >> 2, ak0 = (tid & 3) * 4, ar1 = ar0 + 64;
    int bk0 = tid >> 5, bc0 = (tid & 31) * 4, bk1 = bk0 + 8;

    float4 a0v, a1v, b0v, b1v;
#define LOAD_REGS(K0) do { \
        a0v = *(const float4*)(A + (long long)(m0 + ar0) * HH + (K0) + ak0); \
        a1v = *(const float4*)(A + (long long)(m0 + ar1) * HH + (K0) + ak0); \
        b0v = *(const float4*)(Bm + (long long)((K0) + bk0) * HH + c0 + bc0); \
        b1v = *(const float4*)(Bm + (long long)((K0) + bk1) * HH + c0 + bc0); \
    } while (0)
#define STORE_SMEM(BUF) do { \
        As[BUF][ak0+0][ar0] = a0v.x; As[BUF][ak0+1][ar0] = a0v.y; \
        As[BUF][ak0+2][ar0] = a0v.z; As[BUF][ak0+3][ar0] = a0v.w; \
        As[BUF][ak0+0][ar1] = a1v.x; As[BUF][ak0+1][ar1] = a1v.y; \
        As[BUF][ak0+2][ar1] = a1v.z; As[BUF][ak0+3][ar1] = a1v.w; \
        *(float4*)&Bs[BUF][bk0][bc0] = b0v; \
        *(float4*)&Bs[BUF][bk1][bc0] = b1v; \
    } while (0)

    u64 acc2[4][8];
    #pragma unroll
    for (int i = 0; i < 4; i++)
        #pragma unroll
        for (int j = 0; j < 8; j++) acc2[i][j] = 0ULL;

    LOAD_REGS(kbase);
    STORE_SMEM(0);
    __syncthreads();

    const int NT = (HH / 4) / TK;  // 12
    for (int kt = 0; kt < NT; kt++) {
        int cur = kt & 1;
        if (kt + 1 < NT) LOAD_REGS(kbase + (kt + 1) * TK);
        #pragma unroll
        for (int kk = 0; kk < TK; kk++) {
            const float* bsp = &Bs[cur][kk][tx * 8];
            float4 bA = *(const float4*)bsp;
            float4 bB = *(const float4*)(bsp + 4);
            u64 bb[8] = { pk2(bA.x,bA.x), pk2(bA.y,bA.y), pk2(bA.z,bA.z), pk2(bA.w,bA.w),
                          pk2(bB.x,bB.x), pk2(bB.y,bB.y), pk2(bB.z,bB.z), pk2(bB.w,bB.w) };
            const u64* asp = (const u64*)&As[cur][kk][ty * 8];
            u64 a2[4] = { asp[0], asp[1], asp[2], asp[3] };
            #pragma unroll
            for (int i = 0; i < 4; i++)
                #pragma unroll
                for (int j = 0; j < 8; j++)
                    acc2[i][j] = fma2(a2[i], bb[j], acc2[i][j]);
        }
        if (kt + 1 < NT) { STORE_SMEM(cur ^ 1); __syncthreads(); }
    }

    #pragma unroll
    for (int i2 = 0; i2 < 4; i2++) {
        int r0 = m0 + ty * 8 + i2 * 2;
        #pragma unroll
        for (int j = 0; j < 8; j++) {
            float lo, hi; upk2(acc2[i2][j], lo, hi);
            int c = c0 + tx * 8 + j;
            atomicAdd(&g_Wc[(long long)r0 * HH + c], lo);
            atomicAdd(&g_Wc[(long long)(r0 + 1) * HH + c], hi);
        }
    }
#undef LOAD_REGS
#undef STORE_SMEM
}

// ---------------- 3b) main gathered SGEMM: 128x128 tile, packed FFMA2 ------
__global__ __launch_bounds__(256)
void sgemm128(const float* __restrict__ A0, const float* __restrict__ B0,
              const float* __restrict__ bias0, float* __restrict__ C0, const int* __restrict__ g0,
              const float* __restrict__ A1, const float* __restrict__ B1,
              const float* __restrict__ bias1, float* __restrict__ C1, const int* __restrict__ g1) {
    __shared__ __align__(16) float As[2][TK][132];
    __shared__ __align__(16) float Bs[2][TK][128];
    __shared__ long long rowbase[128];

    const float* A; const float* Bm; const float* bias; float* C; const int* gidx;
    if (blockIdx.z == 0) { A = A0; Bm = B0; bias = bias0; C = C0; gidx = g0; }
    else                 { A = A1; Bm = B1; bias = bias1; C = C1; gidx = g1; }

    int tid = threadIdx.x;
    int tx = tid & 15, ty = tid >> 4;
    int m0 = blockIdx.y * 128, c0 = blockIdx.x * 128;

    if (tid < 128) {
        int m = m0 + tid;
        int b = m >> 7;
        rowbase[tid] = ((long long)b * SS + gidx[m]) * HH;
    }
    __syncthreads();

    int ar0 = tid >> 2, ak0 = (tid & 3) * 4, ar1 = ar0 + 64;
    int bk0 = tid >> 5, bc0 = (tid & 31) * 4, bk1 = bk0 + 8;
    long long ra0 = rowbase[ar0];
    long long ra1 = rowbase[ar1];

    float4 a0v, a1v, b0v, b1v;
#define LOAD_REGS(K0) do { \
        a0v = *(const float4*)(A + ra0 + (K0) + ak0); \
        a1v = *(const float4*)(A + ra1 + (K0) + ak0); \
        b0v = *(const float4*)(Bm + (long long)((K0) + bk0) * HH + c0 + bc0); \
        b1v = *(const float4*)(Bm + (long long)((K0) + bk1) * HH + c0 + bc0); \
    } while (0)
#define STORE_SMEM(BUF) do { \
        As[BUF][ak0+0][ar0] = a0v.x; As[BUF][ak0+1][ar0] = a0v.y; \
        As[BUF][ak0+2][ar0] = a0v.z; As[BUF][ak0+3][ar0] = a0v.w; \
        As[BUF][ak0+0][ar1] = a1v.x; As[BUF][ak0+1][ar1] = a1v.y; \
        As[BUF][ak0+2][ar1] = a1v.z; As[BUF][ak0+3][ar1] = a1v.w; \
        *(float4*)&Bs[BUF][bk0][bc0] = b0v; \
        *(float4*)&Bs[BUF][bk1][bc0] = b1v; \
    } while (0)

    u64 acc2[4][8];
    #pragma unroll
    for (int i = 0; i < 4; i++)
        #pragma unroll
        for (int j = 0; j < 8; j++) acc2[i][j] = 0ULL;

    LOAD_REGS(0);
    STORE_SMEM(0);
    __syncthreads();

    const int NT = HH / TK;   // 48
    for (int kt = 0; kt < NT; kt++) {
        int cur = kt & 1;
        if (kt + 1 < NT) LOAD_REGS((kt + 1) * TK);
        #pragma unroll
        for (int kk = 0; kk < TK; kk++) {
            const float* bsp = &Bs[cur][kk][tx * 8];
            float4 bA = *(const float4*)bsp;
            float4 bB = *(const float4*)(bsp + 4);
            u64 bb[8] = { pk2(bA.x,bA.x), pk2(bA.y,bA.y), pk2(bA.z,bA.z), pk2(bA.w,bA.w),
                          pk2(bB.x,bB.x), pk2(bB.y,bB.y), pk2(bB.z,bB.z), pk2(bB.w,bB.w) };
            const u64* asp = (const u64*)&As[cur][kk][ty * 8];
            u64 a2[4] = { asp[0], asp[1], asp[2], asp[3] };
            #pragma unroll
            for (int i = 0; i < 4; i++)
                #pragma unroll
                for (int j = 0; j < 8; j++)
                    acc2[i][j] = fma2(a2[i], bb[j], acc2[i][j]);
        }
        if (kt + 1 < NT) { STORE_SMEM(cur ^ 1); __syncthreads(); }
    }

    float bv8[8];
    #pragma unroll
    for (int j = 0; j < 8; j++) bv8[j] = bias[c0 + tx * 8 + j];

    #pragma unroll
    for (int i2 = 0; i2 < 4; i2++) {
        float lo[8], hi[8];
        #pragma unroll
        for (int j = 0; j < 8; j++) upk2(acc2[i2][j], lo[j], hi[j]);
        int r0 = m0 + ty * 8 + i2 * 2;
        float4 v;
        v.x = lo[0]+bv8[0]; v.y = lo[1]+bv8[1]; v.z = lo[2]+bv8[2]; v.w = lo[3]+bv8[3];
        *(float4*)&C[(long long)r0 * HH + c0 + tx * 8] = v;
        v.x = lo[4]+bv8[4]; v.y = lo[5]+bv8[5]; v.z = lo[6]+bv8[6]; v.w = lo[7]+bv8[7];
        *(float4*)&C[(long long)r0 * HH + c0 + tx * 8 + 4] = v;
        v.x = hi[0]+bv8[0]; v.y = hi[1]+bv8[1]; v.z = hi[2]+bv8[2]; v.w = hi[3]+bv8[3];
        *(float4*)&C[(long long)(r0+1) * HH + c0 + tx * 8] = v;
        v.x = hi[4]+bv8[4]; v.y = hi[5]+bv8[5]; v.z = hi[6]+bv8[6]; v.w = hi[7]+bv8[7];
        *(float4*)&C[(long long)(r0+1) * HH + c0 + tx * 8 + 4] = v;
    }
#undef LOAD_REGS
#undef STORE_SMEM
}

// ---------------- 4) biaffine split-K: g_biaf[b,i,j] += tmp[b,i,:k] . val[b,j,:k]
__global__ __launch_bounds__(256)
void biaf_splitk() {
    __shared__ __align__(16) float As[2][TK][132];
    __shared__ __align__(16) float Bs[2][TK][132];

    int b = blockIdx.y;
    int kbase = blockIdx.x * (HH / 4);     // 192
    int tid = threadIdx.x;
    int tx = tid & 15, ty = tid >> 4;

    const float* A = g_tmp     + (long long)b * MC * HH;
    const float* V = g_valreps + (long long)b * MC * HH;

    int ar0 = tid >> 2, ak0 = (tid & 3) * 4, ar1 = ar0 + 64;

    float4 a0v, a1v, b0v, b1v;
#define LOAD_REGS(K0) do { \
        a0v = *(const float4*)(A + (long long)ar0 * HH + (K0) + ak0); \
        a1v = *(const float4*)(A + (long long)ar1 * HH + (K0) + ak0); \
        b0v = *(const float4*)(V + (long long)ar0 * HH + (K0) + ak0); \
        b1v = *(const float4*)(V + (long long)ar1 * HH + (K0) + ak0); \
    } while (0)
#define STORE_SMEM(BUF) do { \
        As[BUF][ak0+0][ar0] = a0v.x; As[BUF][ak0+1][ar0] = a0v.y; \
        As[BUF][ak0+2][ar0] = a0v.z; As[BUF][ak0+3][ar0] = a0v.w; \
        As[BUF][ak0+0][ar1] = a1v.x; As[BUF][ak0+1][ar1] = a1v.y; \
        As[BUF][ak0+2][ar1] = a1v.z; As[BUF][ak0+3][ar1] = a1v.w; \
        Bs[BUF][ak0+0][ar0] = b0v.x; Bs[BUF][ak0+1][ar0] = b0v.y; \
        Bs[BUF][ak0+2][ar0] = b0v.z; Bs[BUF][ak0+3][ar0] = b0v.w; \
        Bs[BUF][ak0+0][ar1] = b1v.x; Bs[BUF][ak0+1][ar1] = b1v.y; \
        Bs[BUF][ak0+2][ar1] = b1v.z; Bs[BUF][ak0+3][ar1] = b1v.w; \
    } while (0)

    u64 acc2[4][8];
    #pragma unroll
    for (int i = 0; i < 4; i++)
        #pragma unroll
        for (int j = 0; j < 8; j++) acc2[i][j] = 0ULL;

    LOAD_REGS(kbase);
    STORE_SMEM(0);
    __syncthreads();

    const int NT = (HH / 4) / TK;  // 12
    for (int kt = 0; kt < NT; kt++) {
        int cur = kt & 1;
        if (kt + 1 < NT) LOAD_REGS(kbase + (kt + 1) * TK);
        #pragma unroll
        for (int kk = 0; kk < TK; kk++) {
            const float* bsp = &Bs[cur][kk][tx * 8];
            float4 bA = *(const float4*)bsp;
            float4 bB = *(const float4*)(bsp + 4);
            u64 bb[8] = { pk2(bA.x,bA.x), pk2(bA.y,bA.y), pk2(bA.z,bA.z), pk2(bA.w,bA.w),
                          pk2(bB.x,bB.x), pk2(bB.y,bB.y), pk2(bB.z,bB.z), pk2(bB.w,bB.w) };
            const u64* asp = (const u64*)&As[cur][kk][ty * 8];
            u64 a2[4] = { asp[0], asp[1], asp[2], asp[3] };
            #pragma unroll
            for (int i = 0; i < 4; i++)
                #pragma unroll
                for (int j = 0; j < 8; j++)
                    acc2[i][j] = fma2(a2[i], bb[j], acc2[i][j]);
        }
        if (kt + 1 < NT) { STORE_SMEM(cur ^ 1); __syncthreads(); }
    }

    float* dst = g_biaf + (long long)b * (MC * MC);
    #pragma unroll
    for (int i2 = 0; i2 < 4; i2++) {
        int r0 = ty * 8 + i2 * 2;
        #pragma unroll
        for (int j = 0; j < 8; j++) {
            float lo, hi; upk2(acc2[i2][j], lo, hi);
            int c = tx * 8 + j;
            atomicAdd(&dst[r0 * MC + c], lo);
            atomicAdd(&dst[(r0 + 1) * MC + c], hi);
        }
    }
#undef LOAD_REGS
#undef STORE_SMEM
}

// ---------------- 5) spatial features + MLP, packed over j pairs ----------
__global__ __launch_bounds__(128)
void pair_kernel(float* __restrict__ out,
                 const float* __restrict__ Ws1, const float* __restrict__ bs1,
                 const float* __restrict__ Ws2, const float* __restrict__ bs2,
                 const float* __restrict__ Wf1, const float* __restrict__ bf1,
                 const float* __restrict__ Wf2, const float* __restrict__ bf2,
                 const float* __restrict__ bbilp) {
    __shared__ u64 sW1d[8 * 64];
    __shared__ u64 sW2d[64 * 32];
    __shared__ u64 sF1d[33 * 16];
    __shared__ u64 sF2d[16];
    __shared__ float sb1[64], sb2[32], sb3[16];
    __shared__ float sbf2, sbil;
    __shared__ float kb[2][4];

    int t = threadIdx.x;
    int ty = t >> 6;           // which of 2 key rows
    int tx = t & 63;           // j pair index
    int b = blockIdx.y;
    int i = blockIdx.x * 2 + ty;

    for (int s = t; s < 512;  s += 128) { float w = Ws1[s]; sW1d[s] = pk2(w, w); }
    for (int s = t; s < 2048; s += 128) { float w = Ws2[s]; sW2d[s] = pk2(w, w); }
    for (int s = t; s < 528;  s += 128) { float w = Wf1[s]; sF1d[s] = pk2(w, w); }
    if (t < 64) sb1[t] = bs1[t];
    if (t < 32) sb2[t] = bs2[t];
    if (t < 16) { sb3[t] = bf1[t]; float w = Wf2[t]; sF2d[t] = pk2(w, w); }
    if (t == 0) { sbf2 = bf2[0]; sbil = bbilp[0]; }
    if (t < 8)  kb[t >> 2][t & 3] = g_kbox[(b * MC + blockIdx.x * 2 + (t >> 2)) * 4 + (t & 3)];
    __syncthreads();

    float kx1 = kb[ty][0], ky1 = kb[ty][1], kx2 = kb[ty][2], ky2 = kb[ty][3];
    float kcx = (kx1 + kx2) * 0.5f, kcy = (ky1 + ky2) * 0.5f;
    float kh = ky2 - ky1, kw = kx2 - kx1;

    int j0 = tx * 2;
    float fa[2][8];
    #pragma unroll
    for (int s = 0; s < 2; s++) {
        const float* vb = g_vbox + (long long)(b * MC + j0 + s) * 4;
        float vx1 = vb[0], vy1 = vb[1], vx2 = vb[2], vy2 = vb[3];
        float vcx = (vx1 + vx2) * 0.5f, vcy = (vy1 + vy2) * 0.5f;
        float dx = vcx - kcx, dy = vcy - kcy;
        float dist  = sqrtf(dx * dx + dy * dy + EPSF);
        float angle = atan2f(dy, dx);
        float vh = vy2 - vy1, vw = vx2 - vx1;
        float h_ov = fmaxf(fminf(ky2, vy2) - fmaxf(ky1, vy1), 0.0f);
        float h_align = h_ov / (fminf(kh, vh) + EPSF);
        float v_ov = fmaxf(fminf(kx2, vx2) - fmaxf(kx1, vx1), 0.0f);
        float v_align = v_ov / (fminf(kw, vw) + EPSF);
        float area_ratio   = (vh * vw) / (kh * kw + EPSF);
        float aspect_ratio = (vw / (vh + EPSF)) / (kw / (kh + EPSF));
        fa[s][0] = dx; fa[s][1] = dy; fa[s][2] = dist; fa[s][3] = angle;
        fa[s][4] = h_align; fa[s][5] = v_align; fa[s][6] = area_ratio; fa[s][7] = aspect_ratio;
    }
    u64 sf2[8];
    #pragma unroll
    for (int f = 0; f < 8; f++) sf2[f] = pk2(fa[0][f], fa[1][f]);

    u64 h2p[32];
    #pragma unroll
    for (int t2 = 0; t2 < 32; t2++) h2p[t2] = pk2(sb2[t2], sb2[t2]);

    for (int u = 0; u < 64; u++) {
        u64 h = pk2(sb1[u], sb1[u]);
        #pragma unroll
        for (int f = 0; f < 8; f++) h = fma2(sf2[f], sW1d[f * 64 + u], h);
        h = relu2(h);
        #pragma unroll
        for (int t2 = 0; t2 < 32; t2++) h2p[t2] = fma2(h, sW2d[u * 32 + t2], h2p[t2]);
    }

    long long oidx = (long long)b * (MC * MC) + i * MC + j0;
    u64 braw = *(const u64*)&g_biaf[oidx];
    u64 biaf2 = add2(braw, pk2(sbil, sbil));

    u64 f1p[16];
    #pragma unroll
    for (int tt = 0; tt < 16; tt++)
        f1p[tt] = fma2(biaf2, sF1d[tt], pk2(sb3[tt], sb3[tt]));
    for (int t2 = 0; t2 < 32; t2++) {
        u64 hv = h2p[t2];
        #pragma unroll
        for (int tt = 0; tt < 16; tt++)
            f1p[tt] = fma2(hv, sF1d[(t2 + 1) * 16 + tt], f1p[tt]);
    }

    u64 sc = pk2(sbf2, sbf2);
    #pragma unroll
    for (int tt = 0; tt < 16; tt++) sc = fma2(relu2(f1p[tt]), sF2d[tt], sc);

    float s0, s1; upk2(sc, s0, s1);
    out[oidx]     = s0;
    out[oidx + 1] = s1;
}

// ---------------- launch ----------------
extern "C" void kernel_launch(void* const* d_in, const int* in_sizes, int n_in,
                              void* d_out, int out_size) {
    (void)in_sizes; (void)n_in; (void)out_size;
    const float* seq    = (const float*)d_in[0];
    const float* logits = (const float*)d_in[1];
    const float* bboxes = (const float*)d_in[2];
    const int*   mask   = (const int*)  d_in[3];
    const float* Wk  = (const float*)d_in[4];
    const float* bk  = (const float*)d_in[5];
    const float* Wv  = (const float*)d_in[6];
    const float* bv  = (const float*)d_in[7];
    const float* Wbil= (const float*)d_in[8];
    const float* bbil= (const float*)d_in[9];
    const float* Ws1 = (const float*)d_in[10];
    const float* bs1 = (const float*)d_in[11];
    const float* Ws2 = (const float*)d_in[12];
    const float* bs2 = (const float*)d_in[13];
    const float* Wf1 = (const float*)d_in[14];
    const float* bf1 = (const float*)d_in[15];
    const float* Wf2 = (const float*)d_in[16];
    const float* bf2 = (const float*)d_in[17];
    float* out = (float*)d_out;

    float *pWc, *pbc, *pvrep, *ptmp, *pbiaf; int *pkidx, *pvidx;
    cudaGetSymbolAddress((void**)&pWc,  g_Wc);
    cudaGetSymbolAddress((void**)&pbc,  g_bc);
    cudaGetSymbolAddress((void**)&pvrep,g_valreps);
    cudaGetSymbolAddress((void**)&ptmp, g_tmp);
    cudaGetSymbolAddress((void**)&pbiaf,g_biaf);
    cudaGetSymbolAddress((void**)&pkidx,g_kidx);
    cudaGetSymbolAddress((void**)&pvidx,g_vidx);

    cudaMemsetAsync(pWc,   0, (size_t)HH * HH * sizeof(float));
    cudaMemsetAsync(pbiaf, 0, (size_t)BB * MC * MC * sizeof(float));

    conf_kernel<<<(BB * SS + 255) / 256, 256>>>(logits, mask);
    topk_kernel<<<dim3(BB, 2), 512>>>(bboxes, out);
    bc_kernel<<<HH / 128, 128>>>(bk, Wbil);

    // Wc = Wk @ Wbil, split-K x4 (144 blocks)
    wc_splitk<<<dim3(HH / 128, HH / 128, 4), 256>>>(Wk, Wbil);

    // z=0: val_reps = gather_v(seq) @ Wv + bv
    // z=1: tmp      = gather_k(seq) @ Wc + bc
    sgemm128<<<dim3(HH / 128, (BB * MC) / 128, 2), 256>>>(
        seq, Wv,  bv,  pvrep, pvidx,
        seq, pWc, pbc, ptmp,  pkidx);

    biaf_splitk<<<dim3(4, BB), 256>>>();

    pair_kernel<<<dim3(MC / 2, BB), 128>>>(out, Ws1, bs1, Ws2, bs2,
                                           Wf1, bf1, Wf2, bf2, bbil);
}

// round 4
// speedup vs baseline: 1.4797x; 1.4797x over previous
#include <cuda_runtime.h>
#include <math.h>

#define BB 32
#define SS 512
#define HH 768
#define MC 128
#define EPSF 1e-8f
#define TK 16

// ---------------- scratch (static device memory; no allocs) ----------------
__device__ float g_keyconf[BB*SS];
__device__ float g_valconf[BB*SS];
__device__ int   g_kidx[BB*MC];
__device__ int   g_vidx[BB*MC];
__device__ float g_kbox[BB*MC*4];
__device__ float g_vbox[BB*MC*4];
__device__ float g_valreps[BB*MC*HH];
__device__ float g_tmp[BB*MC*HH];
__device__ float g_biaf[BB*MC*MC];
__device__ float g_Wc[HH*HH];
__device__ float g_bc[HH];

// ---------------- 1) softmax + argmax + mask ----------------
__global__ void conf_kernel(const float* __restrict__ logits,
                            const int* __restrict__ mask) {
    int t = blockIdx.x * blockDim.x + threadIdx.x;
    if (t >= BB * SS) return;
    float l0 = logits[3*t+0], l1 = logits[3*t+1], l2 = logits[3*t+2];
    int pred = 0; float best = l0;
    if (l1 > best) { pred = 1; best = l1; }
    if (l2 > best) { pred = 2; best = l2; }
    float e0 = expf(l0 - best), e1 = expf(l1 - best), e2 = expf(l2 - best);
    float inv = 1.0f / (e0 + e1 + e2);
    bool valid = (mask[t] == 1);
    float ninf = -INFINITY;
    g_keyconf[t] = (pred == 1 && valid) ? e1 * inv : ninf;
    g_valconf[t] = (pred == 2 && valid) ? e2 * inv : ninf;
}

// ---------------- 2) exact top-128 of 512 via bitonic sort ----------------
__global__ void topk_kernel(const float* __restrict__ bboxes,
                            float* __restrict__ out) {
    int b = blockIdx.x;
    int which = blockIdx.y;   // 0 = key, 1 = val
    const float* conf = (which == 0) ? g_keyconf : g_valconf;
    __shared__ float sc[512];
    __shared__ int   si[512];
    int tid = threadIdx.x;
    sc[tid] = conf[b * SS + tid];
    si[tid] = tid;

    for (int k = 2; k <= 512; k <<= 1) {
        for (int j = k >> 1; j > 0; j >>= 1) {
            __syncthreads();
            int ixj = tid ^ j;
            if (ixj > tid) {
                float c1 = sc[tid], c2 = sc[ixj];
                int   i1 = si[tid], i2 = si[ixj];
                bool b2 = (c2 > c1) || (c2 == c1 && i2 < i1);
                bool doswap = ((tid & k) == 0) ? b2 : !b2;
                if (doswap) {
                    sc[tid] = c2; si[tid] = i2;
                    sc[ixj] = c1; si[ixj] = i1;
                }
            }
        }
    }
    __syncthreads();

    if (tid < MC) {
        int   idx = si[tid];
        float cf  = sc[tid];
        int*   gi = (which == 0) ? g_kidx : g_vidx;
        float* gb = (which == 0) ? g_kbox : g_vbox;
        gi[b * MC + tid] = idx;
        const float* src = bboxes + ((long long)b * SS + idx) * 4;
        float* dst = gb + (b * MC + tid) * 4;
        dst[0] = src[0]; dst[1] = src[1]; dst[2] = src[2]; dst[3] = src[3];
        long long base = (long long)BB * MC * MC;            // 524288
        float vf = (cf != -INFINITY) ? 1.0f : 0.0f;
        out[base + (long long)which * (BB * MC) + b * MC + tid] = vf;
        out[base + 2LL * (BB * MC) + (long long)which * (BB * MC) + b * MC + tid] = (float)idx;
    }
}

// ---------------- bc[j] = sum_h bk[h] * Wbil[h,j] ----------------
__global__ void bc_kernel(const float* __restrict__ bk,
                          const float* __restrict__ Wbil) {
    int j = blockIdx.x * 128 + threadIdx.x;
    float s = 0.0f;
    for (int h = 0; h < HH; h++) s = fmaf(bk[h], Wbil[h * HH + j], s);
    g_bc[j] = s;
}

// ---------------- 3a) Wc = Wk @ Wbil, split-K x4, scalar FMA --------------
__global__ __launch_bounds__(256)
void wc_splitk(const float* __restrict__ A, const float* __restrict__ Bm) {
    __shared__ __align__(16) float As[2][TK][132];
    __shared__ __align__(16) float Bs[2][TK][128];
    int tid = threadIdx.x;
    int tx = tid & 15, ty = tid >> 4;
    int m0 = blockIdx.y * 128, c0 = blockIdx.x * 128;
    int kbase = blockIdx.z * (HH / 4);       // 192 per split
    int ar0 = tid >> 2, ak0 = (tid & 3) * 4, ar1 = ar0 + 64;
    int bk0 = tid >> 5, bc0 = (tid & 31) * 4, bk1 = bk0 + 8;

    float4 a0v, a1v, b0v, b1v;
#define LOAD_REGS(K0) do { \
        a0v = *(const float4*)(A + (long long)(m0 + ar0) * HH + (K0) + ak0); \
        a1v = *(const float4*)(A + (long long)(m0 + ar1) * HH + (K0) + ak0); \
        b0v = *(const float4*)(Bm + (long long)((K0) + bk0) * HH + c0 + bc0); \
        b1v = *(const float4*)(Bm + (long long)((K0) + bk1) * HH + c0 + bc0); \
    } while (0)
#define STORE_SMEM(BUF) do { \
        As[BUF][ak0+0][ar0] = a0v.x; As[BUF][ak0+1][ar0] = a0v.y; \
        As[BUF][ak0+2][ar0] = a0v.z; As[BUF][ak0+3][ar0] = a0v.w; \
        As[BUF][ak0+0][ar1] = a1v.x; As[BUF][ak0+1][ar1] = a1v.y; \
        As[BUF][ak0+2][ar1] = a1v.z; As[BUF][ak0+3][ar1] = a1v.w; \
        *(float4*)&Bs[BUF][bk0][bc0] = b0v; \
        *(float4*)&Bs[BUF][bk1][bc0] = b1v; \
    } while (0)

    float acc[8][8];
    #pragma unroll
    for (int i = 0; i < 8; i++)
        #pragma unroll
        for (int j = 0; j < 8; j++) acc[i][j] = 0.0f;

    LOAD_REGS(kbase);
    STORE_SMEM(0);
    __syncthreads();

    const int NT = (HH / 4) / TK;  // 12
    for (int kt = 0; kt < NT; kt++) {
        int cur = kt & 1;
        if (kt + 1 < NT) LOAD_REGS(kbase + (kt + 1) * TK);
        #pragma unroll
        for (int kk = 0; kk < TK; kk++) {
            float a[8], b[8];
            *(float4*)(a)     = *(const float4*)&As[cur][kk][ty * 8];
            *(float4*)(a + 4) = *(const float4*)&As[cur][kk][ty * 8 + 4];
            *(float4*)(b)     = *(const float4*)&Bs[cur][kk][tx * 8];
            *(float4*)(b + 4) = *(const float4*)&Bs[cur][kk][tx * 8 + 4];
            #pragma unroll
            for (int i = 0; i < 8; i++)
                #pragma unroll
                for (int j = 0; j < 8; j++)
                    acc[i][j] = fmaf(a[i], b[j], acc[i][j]);
        }
        if (kt + 1 < NT) { STORE_SMEM(cur ^ 1); __syncthreads(); }
    }

    #pragma unroll
    for (int i = 0; i < 8; i++) {
        int r = m0 + ty * 8 + i;
        #pragma unroll
        for (int j = 0; j < 8; j++) {
            int c = c0 + tx * 8 + j;
            atomicAdd(&g_Wc[(long long)r * HH + c], acc[i][j]);
        }
    }
#undef LOAD_REGS
#undef STORE_SMEM
}

// ---------------- 3b) main gathered SGEMM: 128x128 tile, 8x8, scalar ------
__global__ __launch_bounds__(256)
void sgemm128(const float* __restrict__ A0, const float* __restrict__ B0,
              const float* __restrict__ bias0, float* __restrict__ C0, const int* __restrict__ g0,
              const float* __restrict__ A1, const float* __restrict__ B1,
              const float* __restrict__ bias1, float* __restrict__ C1, const int* __restrict__ g1) {
    __shared__ __align__(16) float As[2][TK][132];
    __shared__ __align__(16) float Bs[2][TK][128];
    __shared__ long long rowbase[128];

    const float* A; const float* Bm; const float* bias; float* C; const int* gidx;
    if (blockIdx.z == 0) { A = A0; Bm = B0; bias = bias0; C = C0; gidx = g0; }
    else                 { A = A1; Bm = B1; bias = bias1; C = C1; gidx = g1; }

    int tid = threadIdx.x;
    int tx = tid & 15, ty = tid >> 4;
    int m0 = blockIdx.y * 128, c0 = blockIdx.x * 128;

    if (tid < 128) {
        int m = m0 + tid;
        int b = m >> 7;
        rowbase[tid] = ((long long)b * SS + gidx[m]) * HH;
    }
    __syncthreads();

    int ar0 = tid >> 2, ak0 = (tid & 3) * 4, ar1 = ar0 + 64;
    int bk0 = tid >> 5, bc0 = (tid & 31) * 4, bk1 = bk0 + 8;
    long long ra0 = rowbase[ar0];
    long long ra1 = rowbase[ar1];

    float4 a0v, a1v, b0v, b1v;
#define LOAD_REGS(K0) do { \
        a0v = *(const float4*)(A + ra0 + (K0) + ak0); \
        a1v = *(const float4*)(A + ra1 + (K0) + ak0); \
        b0v = *(const float4*)(Bm + (long long)((K0) + bk0) * HH + c0 + bc0); \
        b1v = *(const float4*)(Bm + (long long)((K0) + bk1) * HH + c0 + bc0); \
    } while (0)
#define STORE_SMEM(BUF) do { \
        As[BUF][ak0+0][ar0] = a0v.x; As[BUF][ak0+1][ar0] = a0v.y; \
        As[BUF][ak0+2][ar0] = a0v.z; As[BUF][ak0+3][ar0] = a0v.w; \
        As[BUF][ak0+0][ar1] = a1v.x; As[BUF][ak0+1][ar1] = a1v.y; \
        As[BUF][ak0+2][ar1] = a1v.z; As[BUF][ak0+3][ar1] = a1v.w; \
        *(float4*)&Bs[BUF][bk0][bc0] = b0v; \
        *(float4*)&Bs[BUF][bk1][bc0] = b1v; \
    } while (0)

    float acc[8][8];
    #pragma unroll
    for (int i = 0; i < 8; i++)
        #pragma unroll
        for (int j = 0; j < 8; j++) acc[i][j] = 0.0f;

    LOAD_REGS(0);
    STORE_SMEM(0);
    __syncthreads();

    const int NT = HH / TK;   // 48
    for (int kt = 0; kt < NT; kt++) {
        int cur = kt & 1;
        if (kt + 1 < NT) LOAD_REGS((kt + 1) * TK);
        #pragma unroll
        for (int kk = 0; kk < TK; kk++) {
            float a[8], b[8];
            *(float4*)(a)     = *(const float4*)&As[cur][kk][ty * 8];
            *(float4*)(a + 4) = *(const float4*)&As[cur][kk][ty * 8 + 4];
            *(float4*)(b)     = *(const float4*)&Bs[cur][kk][tx * 8];
            *(float4*)(b + 4) = *(const float4*)&Bs[cur][kk][tx * 8 + 4];
            #pragma unroll
            for (int i = 0; i < 8; i++)
                #pragma unroll
                for (int j = 0; j < 8; j++)
                    acc[i][j] = fmaf(a[i], b[j], acc[i][j]);
        }
        if (kt + 1 < NT) { STORE_SMEM(cur ^ 1); __syncthreads(); }
    }

    float bv8[8];
    #pragma unroll
    for (int j = 0; j < 8; j++) bv8[j] = bias[c0 + tx * 8 + j];

    #pragma unroll
    for (int i = 0; i < 8; i++) {
        int r = m0 + ty * 8 + i;
        float4 v0, v1;
        v0.x = acc[i][0] + bv8[0]; v0.y = acc[i][1] + bv8[1];
        v0.z = acc[i][2] + bv8[2]; v0.w = acc[i][3] + bv8[3];
        v1.x = acc[i][4] + bv8[4]; v1.y = acc[i][5] + bv8[5];
        v1.z = acc[i][6] + bv8[6]; v1.w = acc[i][7] + bv8[7];
        *(float4*)&C[(long long)r * HH + c0 + tx * 8]     = v0;
        *(float4*)&C[(long long)r * HH + c0 + tx * 8 + 4] = v1;
    }
#undef LOAD_REGS
#undef STORE_SMEM
}

// ---------------- 4) biaffine split-K, 128x128 tile, scalar FMA -----------
__global__ __launch_bounds__(256)
void biaf_splitk() {
    __shared__ __align__(16) float As[2][TK][132];
    __shared__ __align__(16) float Bs[2][TK][132];

    int b = blockIdx.y;
    int kbase = blockIdx.x * (HH / 4);     // 192
    int tid = threadIdx.x;
    int tx = tid & 15, ty = tid >> 4;

    const float* A = g_tmp     + (long long)b * MC * HH;
    const float* V = g_valreps + (long long)b * MC * HH;

    int ar0 = tid >> 2, ak0 = (tid & 3) * 4, ar1 = ar0 + 64;

    float4 a0v, a1v, b0v, b1v;
#define LOAD_REGS(K0) do { \
        a0v = *(const float4*)(A + (long long)ar0 * HH + (K0) + ak0); \
        a1v = *(const float4*)(A + (long long)ar1 * HH + (K0) + ak0); \
        b0v = *(const float4*)(V + (long long)ar0 * HH + (K0) + ak0); \
        b1v = *(const float4*)(V + (long long)ar1 * HH + (K0) + ak0); \
    } while (0)
#define STORE_SMEM(BUF) do { \
        As[BUF][ak0+0][ar0] = a0v.x; As[BUF][ak0+1][ar0] = a0v.y; \
        As[BUF][ak0+2][ar0] = a0v.z; As[BUF][ak0+3][ar0] = a0v.w; \
        As[BUF][ak0+0][ar1] = a1v.x; As[BUF][ak0+1][ar1] = a1v.y; \
        As[BUF][ak0+2][ar1] = a1v.z; As[BUF][ak0+3][ar1] = a1v.w; \
        Bs[BUF][ak0+0][ar0] = b0v.x; Bs[BUF][ak0+1][ar0] = b0v.y; \
        Bs[BUF][ak0+2][ar0] = b0v.z; Bs[BUF][ak0+3][ar0] = b0v.w; \
        Bs[BUF][ak0+0][ar1] = b1v.x; Bs[BUF][ak0+1][ar1] = b1v.y; \
        Bs[BUF][ak0+2][ar1] = b1v.z; Bs[BUF][ak0+3][ar1] = b1v.w; \
    } while (0)

    float acc[8][8];
    #pragma unroll
    for (int i = 0; i < 8; i++)
        #pragma unroll
        for (int j = 0; j < 8; j++) acc[i][j] = 0.0f;

    LOAD_REGS(kbase);
    STORE_SMEM(0);
    __syncthreads();

    const int NT = (HH / 4) / TK;  // 12
    for (int kt = 0; kt < NT; kt++) {
        int cur = kt & 1;
        if (kt + 1 < NT) LOAD_REGS(kbase + (kt + 1) * TK);
        #pragma unroll
        for (int kk = 0; kk < TK; kk++) {
            float a[8], b[8];
            *(float4*)(a)     = *(const float4*)&As[cur][kk][ty * 8];
            *(float4*)(a + 4) = *(const float4*)&As[cur][kk][ty * 8 + 4];
            *(float4*)(b)     = *(const float4*)&Bs[cur][kk][tx * 8];
            *(float4*)(b + 4) = *(const float4*)&Bs[cur][kk][tx * 8 + 4];
            #pragma unroll
            for (int i = 0; i < 8; i++)
                #pragma unroll
                for (int j = 0; j < 8; j++)
                    acc[i][j] = fmaf(a[i], b[j], acc[i][j]);
        }
        if (kt + 1 < NT) { STORE_SMEM(cur ^ 1); __syncthreads(); }
    }

    float* dst = g_biaf + (long long)b * (MC * MC);
    #pragma unroll
    for (int i = 0; i < 8; i++) {
        int r = ty * 8 + i;
        #pragma unroll
        for (int j = 0; j < 8; j++) {
            int c = tx * 8 + j;
            atomicAdd(&dst[r * MC + c], acc[i][j]);
        }
    }
#undef LOAD_REGS
#undef STORE_SMEM
}

// ---------------- 5) spatial features + MLP + final scores ----------------
__global__ __launch_bounds__(128)
void pair_kernel(float* __restrict__ out,
                 const float* __restrict__ Ws1, const float* __restrict__ bs1,
                 const float* __restrict__ Ws2, const float* __restrict__ bs2,
                 const float* __restrict__ Wf1, const float* __restrict__ bf1,
                 const float* __restrict__ Wf2, const float* __restrict__ bf2,
                 const float* __restrict__ bbilp) {
    __shared__ float sW1[8 * 64], sb1[64];
    __shared__ float sW2[64 * 32], sb2[32];
    __shared__ float sF1[33 * 16], sb3[16], sF2[16];
    __shared__ float sbf2, sbil;
    __shared__ float kb[4];

    int i = blockIdx.x;
    int b = blockIdx.y;
    int j = threadIdx.x;

    for (int t = j; t < 512;  t += 128) sW1[t] = Ws1[t];
    for (int t = j; t < 2048; t += 128) sW2[t] = Ws2[t];
    for (int t = j; t < 528;  t += 128) sF1[t] = Wf1[t];
    if (j < 64) sb1[j] = bs1[j];
    if (j < 32) sb2[j] = bs2[j];
    if (j < 16) { sb3[j] = bf1[j]; sF2[j] = Wf2[j]; }
    if (j == 0) { sbf2 = bf2[0]; sbil = bbilp[0]; }
    if (j < 4)  kb[j] = g_kbox[(b * MC + i) * 4 + j];
    __syncthreads();

    float vx1 = g_vbox[(b * MC + j) * 4 + 0];
    float vy1 = g_vbox[(b * MC + j) * 4 + 1];
    float vx2 = g_vbox[(b * MC + j) * 4 + 2];
    float vy2 = g_vbox[(b * MC + j) * 4 + 3];
    float kx1 = kb[0], ky1 = kb[1], kx2 = kb[2], ky2 = kb[3];

    float kcx = (kx1 + kx2) * 0.5f, kcy = (ky1 + ky2) * 0.5f;
    float vcx = (vx1 + vx2) * 0.5f, vcy = (vy1 + vy2) * 0.5f;
    float dx = vcx - kcx, dy = vcy - kcy;
    float dist  = sqrtf(dx * dx + dy * dy + EPSF);
    float angle = atan2f(dy, dx);
    float kh = ky2 - ky1, kw = kx2 - kx1;
    float vh = vy2 - vy1, vw = vx2 - vx1;
    float h_ov = fmaxf(fminf(ky2, vy2) - fmaxf(ky1, vy1), 0.0f);
    float h_align = h_ov / (fminf(kh, vh) + EPSF);
    float v_ov = fmaxf(fminf(kx2, vx2) - fmaxf(kx1, vx1), 0.0f);
    float v_align = v_ov / (fminf(kw, vw) + EPSF);
    float area_ratio   = (vh * vw) / (kh * kw + EPSF);
    float aspect_ratio = (vw / (vh + EPSF)) / (kw / (kh + EPSF));

    float sf[8] = { dx, dy, dist, angle, h_align, v_align, area_ratio, aspect_ratio };

    float h2[32];
    #pragma unroll
    for (int t = 0; t < 32; t++) h2[t] = sb2[t];

    for (int u = 0; u < 64; u++) {
        float h = sb1[u];
        #pragma unroll
        for (int f = 0; f < 8; f++) h = fmaf(sf[f], sW1[f * 64 + u], h);
        h = fmaxf(h, 0.0f);
        #pragma unroll
        for (int t = 0; t < 32; t++) h2[t] = fmaf(h, sW2[u * 32 + t], h2[t]);
    }

    float biafv = g_biaf[(long long)b * (MC * MC) + i * MC + j] + sbil;

    float f1[16];
    #pragma unroll
    for (int t = 0; t < 16; t++) f1[t] = fmaf(biafv, sF1[t], sb3[t]);
    for (int t2 = 0; t2 < 32; t2++) {
        float hv = h2[t2];
        #pragma unroll
        for (int t = 0; t < 16; t++) f1[t] = fmaf(hv, sF1[(t2 + 1) * 16 + t], f1[t]);
    }

    float score = sbf2;
    #pragma unroll
    for (int t = 0; t < 16; t++) score = fmaf(fmaxf(f1[t], 0.0f), sF2[t], score);

    out[(long long)b * (MC * MC) + i * MC + j] = score;
}

// ---------------- launch ----------------
extern "C" void kernel_launch(void* const* d_in, const int* in_sizes, int n_in,
                              void* d_out, int out_size) {
    (void)in_sizes; (void)n_in; (void)out_size;
    const float* seq    = (const float*)d_in[0];
    const float* logits = (const float*)d_in[1];
    const float* bboxes = (const float*)d_in[2];
    const int*   mask   = (const int*)  d_in[3];
    const float* Wk  = (const float*)d_in[4];
    const float* bk  = (const float*)d_in[5];
    const float* Wv  = (const float*)d_in[6];
    const float* bv  = (const float*)d_in[7];
    const float* Wbil= (const float*)d_in[8];
    const float* bbil= (const float*)d_in[9];
    const float* Ws1 = (const float*)d_in[10];
    const float* bs1 = (const float*)d_in[11];
    const float* Ws2 = (const float*)d_in[12];
    const float* bs2 = (const float*)d_in[13];
    const float* Wf1 = (const float*)d_in[14];
    const float* bf1 = (const float*)d_in[15];
    const float* Wf2 = (const float*)d_in[16];
    const float* bf2 = (const float*)d_in[17];
    float* out = (float*)d_out;

    float *pWc, *pbc, *pvrep, *ptmp, *pbiaf; int *pkidx, *pvidx;
    cudaGetSymbolAddress((void**)&pWc,  g_Wc);
    cudaGetSymbolAddress((void**)&pbc,  g_bc);
    cudaGetSymbolAddress((void**)&pvrep,g_valreps);
    cudaGetSymbolAddress((void**)&ptmp, g_tmp);
    cudaGetSymbolAddress((void**)&pbiaf,g_biaf);
    cudaGetSymbolAddress((void**)&pkidx,g_kidx);
    cudaGetSymbolAddress((void**)&pvidx,g_vidx);

    cudaMemsetAsync(pWc,   0, (size_t)HH * HH * sizeof(float));
    cudaMemsetAsync(pbiaf, 0, (size_t)BB * MC * MC * sizeof(float));

    conf_kernel<<<(BB * SS + 255) / 256, 256>>>(logits, mask);
    topk_kernel<<<dim3(BB, 2), 512>>>(bboxes, out);
    bc_kernel<<<HH / 128, 128>>>(bk, Wbil);

    // Wc = Wk @ Wbil, split-K x4 (144 blocks)
    wc_splitk<<<dim3(HH / 128, HH / 128, 4), 256>>>(Wk, Wbil);

    // z=0: val_reps = gather_v(seq) @ Wv + bv
    // z=1: tmp      = gather_k(seq) @ Wc + bc
    sgemm128<<<dim3(HH / 128, (BB * MC) / 128, 2), 256>>>(
        seq, Wv,  bv,  pvrep, pvidx,
        seq, pWc, pbc, ptmp,  pkidx);

    biaf_splitk<<<dim3(4, BB), 256>>>();

    pair_kernel<<<dim3(MC, BB), 128>>>(out, Ws1, bs1, Ws2, bs2,
                                       Wf1, bf1, Wf2, bf2, bbil);
}